// round 1
// baseline (speedup 1.0000x reference)
#include <cuda_runtime.h>
#include <cstdint>

#define NN 50000
#define DD 128
#define EDIM 16
#define NE 800000

// ---------------- device scratch (no allocations allowed) ----------------
__device__ float g_Wef[EDIM * DD];     // collapsed edge encoder weight [16,128]
__device__ float g_bef[DD];            // collapsed edge encoder bias
__device__ float g_W1[DD * 256];       // Wm1 with BN1 folded
__device__ float g_b1[256];
__device__ float g_W2[256 * DD];       // Wm2 with BN2 folded
__device__ float g_b2[DD];
__device__ float g_acc[(size_t)NN * DD];   // (1+eps)*node + pooled
__device__ float g_t[(size_t)NN * 256];    // hidden activations

// ---------------- prep: collapse edge MLP, fold BNs ----------------
__global__ void prep_kernel(const float* __restrict__ We1, const float* __restrict__ be1,
                            const float* __restrict__ We2, const float* __restrict__ be2,
                            const float* __restrict__ Wm1, const float* __restrict__ bm1,
                            const float* __restrict__ g1, const float* __restrict__ b1,
                            const float* __restrict__ m1, const float* __restrict__ v1,
                            const float* __restrict__ Wm2, const float* __restrict__ bm2,
                            const float* __restrict__ g2, const float* __restrict__ b2,
                            const float* __restrict__ m2, const float* __restrict__ v2) {
    int i = blockIdx.x * blockDim.x + threadIdx.x;

    // Wef[k][d] = sum_j We1[k][j] * We2[j][d]
    if (i < EDIM * DD) {
        int k = i / DD, d = i % DD;
        float s = 0.f;
        for (int j = 0; j < 256; j++) s += We1[k * 256 + j] * We2[j * DD + d];
        g_Wef[i] = s;
    }
    // bef[d] = be2[d] + sum_j be1[j] * We2[j][d]
    if (i < DD) {
        float s = be2[i];
        for (int j = 0; j < 256; j++) s += be1[j] * We2[j * DD + i];
        g_bef[i] = s;
    }
    // fold BN1 into Wm1/bm1
    if (i < DD * 256) {
        int j = i % 256;
        float a = g1[j] * rsqrtf(v1[j] + 1e-3f);
        g_W1[i] = Wm1[i] * a;
    }
    if (i < 256) {
        float a = g1[i] * rsqrtf(v1[i] + 1e-3f);
        g_b1[i] = bm1[i] * a + b1[i] - m1[i] * a;
    }
    // fold BN2 into Wm2/bm2
    if (i < 256 * DD) {
        int j = i % DD;
        float a = g2[j] * rsqrtf(v2[j] + 1e-3f);
        g_W2[i] = Wm2[i] * a;
    }
    if (i < DD) {
        float a = g2[i] * rsqrtf(v2[i] + 1e-3f);
        g_b2[i] = bm2[i] * a + b2[i] - m2[i] * a;
    }
}

// ---------------- init: acc = (1+eps) * node_feat ----------------
__global__ void init_acc_kernel(const float4* __restrict__ node4, const float* __restrict__ eps) {
    int i = blockIdx.x * blockDim.x + threadIdx.x;
    const int n4 = NN * DD / 4;
    float s = 1.f + eps[0];
    float4* a4 = reinterpret_cast<float4*>(g_acc);
    if (i < n4) {
        float4 v = node4[i];
        v.x *= s; v.y *= s; v.z *= s; v.w *= s;
        a4[i] = v;
    }
}

// ---------------- edge: acc[dst] += relu(ef@Wef + bef + node[src]) ----------------
__global__ void __launch_bounds__(512) edge_kernel(const float* __restrict__ efeat,
                                                   const int* __restrict__ src,
                                                   const int* __restrict__ dst,
                                                   const float* __restrict__ node) {
    const int d = threadIdx.x;  // 0..127 = output channel
    // This thread's column of the collapsed weight, held in registers.
    float w[EDIM];
#pragma unroll
    for (int k = 0; k < EDIM; k++) w[k] = g_Wef[k * DD + d];
    const float bias = g_bef[d];

    int e = blockIdx.x * blockDim.y + threadIdx.y;
    const int stride = gridDim.x * blockDim.y;
    for (; e < NE; e += stride) {
        const float4* ep = reinterpret_cast<const float4*>(efeat + (size_t)e * EDIM);
        float4 f0 = ep[0], f1 = ep[1], f2 = ep[2], f3 = ep[3];
        float v = bias;
        v = fmaf(f0.x, w[0], v);  v = fmaf(f0.y, w[1], v);
        v = fmaf(f0.z, w[2], v);  v = fmaf(f0.w, w[3], v);
        v = fmaf(f1.x, w[4], v);  v = fmaf(f1.y, w[5], v);
        v = fmaf(f1.z, w[6], v);  v = fmaf(f1.w, w[7], v);
        v = fmaf(f2.x, w[8], v);  v = fmaf(f2.y, w[9], v);
        v = fmaf(f2.z, w[10], v); v = fmaf(f2.w, w[11], v);
        v = fmaf(f3.x, w[12], v); v = fmaf(f3.y, w[13], v);
        v = fmaf(f3.z, w[14], v); v = fmaf(f3.w, w[15], v);
        int s = src[e];
        int t = dst[e];
        v += __ldg(node + (size_t)s * DD + d);
        v = fmaxf(v, 0.f);
        atomicAdd(g_acc + (size_t)t * DD + d, v);
    }
}

// ---------------- tiled fp32 GEMM: C = act(A@B + bias) ----------------
// BM=BN=128, BK=8, 256 threads, 8x8 per-thread microtile.
__global__ void __launch_bounds__(256) gemm_kernel(const float* __restrict__ A,
                                                   const float* __restrict__ B,
                                                   const float* __restrict__ bias,
                                                   float* __restrict__ C,
                                                   int M, int N, int K, int relu) {
    __shared__ float As[8][128];
    __shared__ float Bs[8][128];

    const int tid = threadIdx.x;
    const int tx = tid % 16;       // col group
    const int ty = tid / 16;       // row group
    const int m0 = blockIdx.x * 128;
    const int n0 = blockIdx.y * 128;

    // A tile load mapping: each thread one float4
    const int ar = tid >> 1;            // 0..127 row within tile
    const int ac = (tid & 1) * 4;       // 0 or 4 col within BK
    // B tile load mapping
    const int br = tid >> 5;            // 0..7
    const int bc = (tid & 31) * 4;      // 0..124

    float acc[8][8];
#pragma unroll
    for (int i = 0; i < 8; i++)
#pragma unroll
        for (int j = 0; j < 8; j++) acc[i][j] = 0.f;

    for (int k0 = 0; k0 < K; k0 += 8) {
        // load A tile (guard rows), store transposed As[k][m]
        float4 av = make_float4(0.f, 0.f, 0.f, 0.f);
        if (m0 + ar < M)
            av = *reinterpret_cast<const float4*>(A + (size_t)(m0 + ar) * K + k0 + ac);
        As[ac + 0][ar] = av.x;
        As[ac + 1][ar] = av.y;
        As[ac + 2][ar] = av.z;
        As[ac + 3][ar] = av.w;
        // load B tile
        float4 bv = *reinterpret_cast<const float4*>(B + (size_t)(k0 + br) * N + n0 + bc);
        *reinterpret_cast<float4*>(&Bs[br][bc]) = bv;
        __syncthreads();

#pragma unroll
        for (int kk = 0; kk < 8; kk++) {
            float4 a0 = *reinterpret_cast<const float4*>(&As[kk][ty * 8]);
            float4 a1 = *reinterpret_cast<const float4*>(&As[kk][ty * 8 + 4]);
            float4 b0 = *reinterpret_cast<const float4*>(&Bs[kk][tx * 8]);
            float4 b1 = *reinterpret_cast<const float4*>(&Bs[kk][tx * 8 + 4]);
            float ar8[8] = {a0.x, a0.y, a0.z, a0.w, a1.x, a1.y, a1.z, a1.w};
            float br8[8] = {b0.x, b0.y, b0.z, b0.w, b1.x, b1.y, b1.z, b1.w};
#pragma unroll
            for (int i = 0; i < 8; i++)
#pragma unroll
                for (int j = 0; j < 8; j++) acc[i][j] = fmaf(ar8[i], br8[j], acc[i][j]);
        }
        __syncthreads();
    }

    // epilogue
    float bj[8];
#pragma unroll
    for (int j = 0; j < 8; j++) bj[j] = bias[n0 + tx * 8 + j];

#pragma unroll
    for (int i = 0; i < 8; i++) {
        int row = m0 + ty * 8 + i;
        if (row < M) {
            float out[8];
#pragma unroll
            for (int j = 0; j < 8; j++) {
                float v = acc[i][j] + bj[j];
                out[j] = relu ? fmaxf(v, 0.f) : v;
            }
            float4* cp = reinterpret_cast<float4*>(C + (size_t)row * N + n0 + tx * 8);
            cp[0] = make_float4(out[0], out[1], out[2], out[3]);
            cp[1] = make_float4(out[4], out[5], out[6], out[7]);
        }
    }
}

// ---------------- launch ----------------
extern "C" void kernel_launch(void* const* d_in, const int* in_sizes, int n_in,
                              void* d_out, int out_size) {
    const float* node  = (const float*)d_in[0];
    const float* efeat = (const float*)d_in[1];
    const int*   src   = (const int*)d_in[2];
    const int*   dst   = (const int*)d_in[3];
    const float* We1 = (const float*)d_in[4];
    const float* be1 = (const float*)d_in[5];
    const float* We2 = (const float*)d_in[6];
    const float* be2 = (const float*)d_in[7];
    const float* eps = (const float*)d_in[8];
    const float* Wm1 = (const float*)d_in[9];
    const float* bm1 = (const float*)d_in[10];
    const float* g1  = (const float*)d_in[11];
    const float* b1  = (const float*)d_in[12];
    const float* m1  = (const float*)d_in[13];
    const float* v1  = (const float*)d_in[14];
    const float* Wm2 = (const float*)d_in[15];
    const float* bm2 = (const float*)d_in[16];
    const float* g2  = (const float*)d_in[17];
    const float* b2  = (const float*)d_in[18];
    const float* m2  = (const float*)d_in[19];
    const float* v2  = (const float*)d_in[20];
    float* out = (float*)d_out;

    prep_kernel<<<128, 256>>>(We1, be1, We2, be2, Wm1, bm1, g1, b1, m1, v1,
                              Wm2, bm2, g2, b2, m2, v2);

    const int n4 = NN * DD / 4;
    init_acc_kernel<<<(n4 + 255) / 256, 256>>>((const float4*)node, eps);

    edge_kernel<<<1184, dim3(128, 4)>>>(efeat, src, dst, node);

    // resolve device pointers for scratch
    float *pacc, *pt, *pW1, *pb1, *pW2, *pb2;
    cudaGetSymbolAddress((void**)&pacc, g_acc);
    cudaGetSymbolAddress((void**)&pt,   g_t);
    cudaGetSymbolAddress((void**)&pW1,  g_W1);
    cudaGetSymbolAddress((void**)&pb1,  g_b1);
    cudaGetSymbolAddress((void**)&pW2,  g_W2);
    cudaGetSymbolAddress((void**)&pb2,  g_b2);

    // t = relu(acc @ W1 + b1)   [50000, 256]
    gemm_kernel<<<dim3((NN + 127) / 128, 256 / 128), 256>>>(pacc, pW1, pb1, pt,
                                                            NN, 256, DD, 1);
    // out = t @ W2 + b2         [50000, 128]
    gemm_kernel<<<dim3((NN + 127) / 128, DD / 128), 256>>>(pt, pW2, pb2, out,
                                                           NN, DD, 256, 0);
}

// round 2
// speedup vs baseline: 1.2674x; 1.2674x over previous
#include <cuda_runtime.h>
#include <cstdint>

#define NN 50000
#define DD 128
#define EDIM 16
#define NE 800000

// ---------------- device scratch (no allocations allowed) ----------------
__device__ float g_Wef[EDIM * DD];     // collapsed edge encoder weight [16,128]
__device__ float g_bef[DD];            // collapsed edge encoder bias
__device__ float g_W1[DD * 256];       // Wm1 with BN1 folded
__device__ float g_b1[256];
__device__ float g_W2[256 * DD];       // Wm2 with BN2 folded
__device__ float g_b2[DD];
__device__ float g_acc[(size_t)NN * DD];   // (1+eps)*node + pooled
__device__ float g_t[(size_t)NN * 256];    // hidden activations

// ---------------- prep: collapse edge MLP, fold BNs ----------------
__global__ void prep_kernel(const float* __restrict__ We1, const float* __restrict__ be1,
                            const float* __restrict__ We2, const float* __restrict__ be2,
                            const float* __restrict__ Wm1, const float* __restrict__ bm1,
                            const float* __restrict__ g1, const float* __restrict__ b1,
                            const float* __restrict__ m1, const float* __restrict__ v1,
                            const float* __restrict__ Wm2, const float* __restrict__ bm2,
                            const float* __restrict__ g2, const float* __restrict__ b2,
                            const float* __restrict__ m2, const float* __restrict__ v2) {
    int i = blockIdx.x * blockDim.x + threadIdx.x;

    if (i < EDIM * DD) {
        int k = i / DD, d = i % DD;
        float s = 0.f;
        for (int j = 0; j < 256; j++) s += We1[k * 256 + j] * We2[j * DD + d];
        g_Wef[i] = s;
    }
    if (i < DD) {
        float s = be2[i];
        for (int j = 0; j < 256; j++) s += be1[j] * We2[j * DD + i];
        g_bef[i] = s;
    }
    if (i < DD * 256) {
        int j = i % 256;
        float a = g1[j] * rsqrtf(v1[j] + 1e-3f);
        g_W1[i] = Wm1[i] * a;
    }
    if (i < 256) {
        float a = g1[i] * rsqrtf(v1[i] + 1e-3f);
        g_b1[i] = bm1[i] * a + b1[i] - m1[i] * a;
    }
    if (i < 256 * DD) {
        int j = i % DD;
        float a = g2[j] * rsqrtf(v2[j] + 1e-3f);
        g_W2[i] = Wm2[i] * a;
    }
    if (i < DD) {
        float a = g2[i] * rsqrtf(v2[i] + 1e-3f);
        g_b2[i] = bm2[i] * a + b2[i] - m2[i] * a;
    }
}

// ---------------- init: acc = (1+eps) * node_feat ----------------
__global__ void init_acc_kernel(const float4* __restrict__ node4, const float* __restrict__ eps) {
    int i = blockIdx.x * blockDim.x + threadIdx.x;
    const int n4 = NN * DD / 4;
    float s = 1.f + eps[0];
    float4* a4 = reinterpret_cast<float4*>(g_acc);
    if (i < n4) {
        float4 v = node4[i];
        v.x *= s; v.y *= s; v.z *= s; v.w *= s;
        a4[i] = v;
    }
}

// ---------------- edge: acc[dst] += relu(ef@Wef + bef + node[src]) ----------------
// 32 lanes per edge, 4 channels per lane, vectorized red.global.add.v4.f32.
__global__ void __launch_bounds__(256) edge_kernel(const float* __restrict__ efeat,
                                                   const int* __restrict__ src,
                                                   const int* __restrict__ dst,
                                                   const float* __restrict__ node) {
    const int lane = threadIdx.x;          // 0..31, handles channels 4*lane..4*lane+3
    float4 w[EDIM];
#pragma unroll
    for (int k = 0; k < EDIM; k++)
        w[k] = *reinterpret_cast<const float4*>(g_Wef + k * DD + lane * 4);
    const float4 bias = *reinterpret_cast<const float4*>(g_bef + lane * 4);

    int e = blockIdx.x * blockDim.y + threadIdx.y;
    const int stride = gridDim.x * blockDim.y;
    for (; e < NE; e += stride) {
        // uniform-address loads: broadcast within the warp, 1 wavefront each
        const float4* ep = reinterpret_cast<const float4*>(efeat + (size_t)e * EDIM);
        float4 f0 = ep[0], f1 = ep[1], f2 = ep[2], f3 = ep[3];
        float ef[EDIM] = {f0.x, f0.y, f0.z, f0.w, f1.x, f1.y, f1.z, f1.w,
                          f2.x, f2.y, f2.z, f2.w, f3.x, f3.y, f3.z, f3.w};
        float4 v = bias;
#pragma unroll
        for (int k = 0; k < EDIM; k++) {
            v.x = fmaf(ef[k], w[k].x, v.x);
            v.y = fmaf(ef[k], w[k].y, v.y);
            v.z = fmaf(ef[k], w[k].z, v.z);
            v.w = fmaf(ef[k], w[k].w, v.w);
        }
        int s = src[e];
        int t = dst[e];
        float4 nf = *reinterpret_cast<const float4*>(node + (size_t)s * DD + lane * 4);
        v.x = fmaxf(v.x + nf.x, 0.f);
        v.y = fmaxf(v.y + nf.y, 0.f);
        v.z = fmaxf(v.z + nf.z, 0.f);
        v.w = fmaxf(v.w + nf.w, 0.f);
        float* p = g_acc + (size_t)t * DD + lane * 4;
        asm volatile("red.global.add.v4.f32 [%0], {%1, %2, %3, %4};"
                     :: "l"(p), "f"(v.x), "f"(v.y), "f"(v.z), "f"(v.w)
                     : "memory");
    }
}

// ---------------- tiled fp32 GEMM: C = act(A@B + bias) ----------------
// BM=BN=128, BK=16, 256 threads, 8x8 microtile, double-buffered smem,
// one __syncthreads per K-iteration.
__global__ void __launch_bounds__(256) gemm_kernel(const float* __restrict__ A,
                                                   const float* __restrict__ B,
                                                   const float* __restrict__ bias,
                                                   float* __restrict__ C,
                                                   int M, int N, int K, int relu) {
    __shared__ float As[2][16][128];
    __shared__ float Bs[2][16][128];

    const int tid = threadIdx.x;
    const int tx = tid % 16;       // col group
    const int ty = tid / 16;       // row group
    const int m0 = blockIdx.x * 128;
    const int n0 = blockIdx.y * 128;

    // Each thread loads 2 float4 of A and 2 float4 of B per K-tile.
    // A tile (128 rows x 16 cols): idx p*256+tid -> row = idx&127, c4 = idx>>7 (0..3)
    // B tile (16 rows x 128 cols): idx -> krow = idx>>5 (0..15), col4 = idx&31

    float acc[8][8];
#pragma unroll
    for (int i = 0; i < 8; i++)
#pragma unroll
        for (int j = 0; j < 8; j++) acc[i][j] = 0.f;

    float4 pa[2], pb[2];

    // prologue: load tile 0 into regs
    {
#pragma unroll
        for (int p = 0; p < 2; p++) {
            int idx = p * 256 + tid;
            int arow = idx & 127, ac4 = idx >> 7;
            pa[p] = make_float4(0.f, 0.f, 0.f, 0.f);
            if (m0 + arow < M)
                pa[p] = *reinterpret_cast<const float4*>(A + (size_t)(m0 + arow) * K + ac4 * 4);
            int krow = idx >> 5, bc4 = idx & 31;
            pb[p] = *reinterpret_cast<const float4*>(B + (size_t)krow * N + n0 + bc4 * 4);
        }
    }
    int s = 0;
    // store tile 0
#pragma unroll
    for (int p = 0; p < 2; p++) {
        int idx = p * 256 + tid;
        int arow = idx & 127, ac4 = idx >> 7;
        As[s][ac4 * 4 + 0][arow] = pa[p].x;
        As[s][ac4 * 4 + 1][arow] = pa[p].y;
        As[s][ac4 * 4 + 2][arow] = pa[p].z;
        As[s][ac4 * 4 + 3][arow] = pa[p].w;
        int krow = idx >> 5, bc4 = idx & 31;
        *reinterpret_cast<float4*>(&Bs[s][krow][bc4 * 4]) = pb[p];
    }
    __syncthreads();

    const int nk = K / 16;
    for (int kt = 0; kt < nk; kt++) {
        // prefetch next tile into regs
        if (kt + 1 < nk) {
            int k0 = (kt + 1) * 16;
#pragma unroll
            for (int p = 0; p < 2; p++) {
                int idx = p * 256 + tid;
                int arow = idx & 127, ac4 = idx >> 7;
                pa[p] = make_float4(0.f, 0.f, 0.f, 0.f);
                if (m0 + arow < M)
                    pa[p] = *reinterpret_cast<const float4*>(A + (size_t)(m0 + arow) * K + k0 + ac4 * 4);
                int krow = idx >> 5, bc4 = idx & 31;
                pb[p] = *reinterpret_cast<const float4*>(B + (size_t)(k0 + krow) * N + n0 + bc4 * 4);
            }
        }
        // compute on buffer s
#pragma unroll
        for (int kk = 0; kk < 16; kk++) {
            float4 a0 = *reinterpret_cast<const float4*>(&As[s][kk][ty * 8]);
            float4 a1 = *reinterpret_cast<const float4*>(&As[s][kk][ty * 8 + 4]);
            float4 b0 = *reinterpret_cast<const float4*>(&Bs[s][kk][tx * 8]);
            float4 b1 = *reinterpret_cast<const float4*>(&Bs[s][kk][tx * 8 + 4]);
            float ar8[8] = {a0.x, a0.y, a0.z, a0.w, a1.x, a1.y, a1.z, a1.w};
            float br8[8] = {b0.x, b0.y, b0.z, b0.w, b1.x, b1.y, b1.z, b1.w};
#pragma unroll
            for (int i = 0; i < 8; i++)
#pragma unroll
                for (int j = 0; j < 8; j++) acc[i][j] = fmaf(ar8[i], br8[j], acc[i][j]);
        }
        // store prefetched tile into the other buffer
        if (kt + 1 < nk) {
            int d = s ^ 1;
#pragma unroll
            for (int p = 0; p < 2; p++) {
                int idx = p * 256 + tid;
                int arow = idx & 127, ac4 = idx >> 7;
                As[d][ac4 * 4 + 0][arow] = pa[p].x;
                As[d][ac4 * 4 + 1][arow] = pa[p].y;
                As[d][ac4 * 4 + 2][arow] = pa[p].z;
                As[d][ac4 * 4 + 3][arow] = pa[p].w;
                int krow = idx >> 5, bc4 = idx & 31;
                *reinterpret_cast<float4*>(&Bs[d][krow][bc4 * 4]) = pb[p];
            }
            __syncthreads();
            s = d;
        }
    }

    // epilogue
    float bj[8];
#pragma unroll
    for (int j = 0; j < 8; j++) bj[j] = bias[n0 + tx * 8 + j];

#pragma unroll
    for (int i = 0; i < 8; i++) {
        int row = m0 + ty * 8 + i;
        if (row < M) {
            float out[8];
#pragma unroll
            for (int j = 0; j < 8; j++) {
                float v = acc[i][j] + bj[j];
                out[j] = relu ? fmaxf(v, 0.f) : v;
            }
            float4* cp = reinterpret_cast<float4*>(C + (size_t)row * N + n0 + tx * 8);
            cp[0] = make_float4(out[0], out[1], out[2], out[3]);
            cp[1] = make_float4(out[4], out[5], out[6], out[7]);
        }
    }
}

// ---------------- launch ----------------
extern "C" void kernel_launch(void* const* d_in, const int* in_sizes, int n_in,
                              void* d_out, int out_size) {
    const float* node  = (const float*)d_in[0];
    const float* efeat = (const float*)d_in[1];
    const int*   src   = (const int*)d_in[2];
    const int*   dst   = (const int*)d_in[3];
    const float* We1 = (const float*)d_in[4];
    const float* be1 = (const float*)d_in[5];
    const float* We2 = (const float*)d_in[6];
    const float* be2 = (const float*)d_in[7];
    const float* eps = (const float*)d_in[8];
    const float* Wm1 = (const float*)d_in[9];
    const float* bm1 = (const float*)d_in[10];
    const float* g1  = (const float*)d_in[11];
    const float* b1  = (const float*)d_in[12];
    const float* m1  = (const float*)d_in[13];
    const float* v1  = (const float*)d_in[14];
    const float* Wm2 = (const float*)d_in[15];
    const float* bm2 = (const float*)d_in[16];
    const float* g2  = (const float*)d_in[17];
    const float* b2  = (const float*)d_in[18];
    const float* m2  = (const float*)d_in[19];
    const float* v2  = (const float*)d_in[20];
    float* out = (float*)d_out;

    prep_kernel<<<128, 256>>>(We1, be1, We2, be2, Wm1, bm1, g1, b1, m1, v1,
                              Wm2, bm2, g2, b2, m2, v2);

    const int n4 = NN * DD / 4;
    init_acc_kernel<<<(n4 + 255) / 256, 256>>>((const float4*)node, eps);

    edge_kernel<<<2368, dim3(32, 8)>>>(efeat, src, dst, node);

    float *pacc, *pt, *pW1, *pb1, *pW2, *pb2;
    cudaGetSymbolAddress((void**)&pacc, g_acc);
    cudaGetSymbolAddress((void**)&pt,   g_t);
    cudaGetSymbolAddress((void**)&pW1,  g_W1);
    cudaGetSymbolAddress((void**)&pb1,  g_b1);
    cudaGetSymbolAddress((void**)&pW2,  g_W2);
    cudaGetSymbolAddress((void**)&pb2,  g_b2);

    // t = relu(acc @ W1 + b1)   [50000, 256]
    gemm_kernel<<<dim3((NN + 127) / 128, 256 / 128), 256>>>(pacc, pW1, pb1, pt,
                                                            NN, 256, DD, 1);
    // out = t @ W2 + b2         [50000, 128]
    gemm_kernel<<<dim3((NN + 127) / 128, DD / 128), 256>>>(pt, pW2, pb2, out,
                                                           NN, DD, 256, 0);
}